// round 14
// baseline (speedup 1.0000x reference)
#include <cuda_runtime.h>
#include <cuda_bf16.h>
#include <cstdint>

// out[n,w,i] = (1/m) * sum_u x[n,u,i] * weight[n,u] * W[u,w]
// Irreps: 256x0e + 128x1o + 64x2e + 32x3o ; DIM=1184, WNUM=480
// R14: warp-specialized producer(4 warps: cp.async + split) /
//      consumer(8 warps: ldsm+mma) with named-barrier ring sync.

#define DIM_ 1184
#define WNUM_ 480
typedef unsigned long long ull;

__device__ __align__(16) __nv_bfloat16 g_bsplit[2 * 87040];

__device__ __forceinline__ void split2(float s0, float s1, uint32_t& h, uint32_t& l) {
    asm("cvt.rn.satfinite.bf16x2.f32 %0, %1, %2;" : "=r"(h) : "f"(s1), "f"(s0));
    float h0 = __uint_as_float(h << 16);
    float h1 = __uint_as_float(h & 0xffff0000u);
    asm("cvt.rn.satfinite.bf16x2.f32 %0, %1, %2;" : "=r"(l) : "f"(s1 - h1), "f"(s0 - h0));
}

__device__ __forceinline__ void cp_async16(uint32_t dst, const void* src) {
    asm volatile("cp.async.cg.shared.global [%0], [%1], 16;" :: "r"(dst), "l"(src));
}
__device__ __forceinline__ void cp_commit() { asm volatile("cp.async.commit_group;"); }
__device__ __forceinline__ void cp_wait1()  { asm volatile("cp.async.wait_group 1;" ::: "memory"); }

__device__ __forceinline__ void ldsm4(uint32_t* r, uint32_t a) {
    asm volatile("ldmatrix.sync.aligned.m8n8.x4.shared.b16 {%0,%1,%2,%3}, [%4];"
                 : "=r"(r[0]), "=r"(r[1]), "=r"(r[2]), "=r"(r[3]) : "r"(a));
}
__device__ __forceinline__ void ldsm4t(uint32_t* r, uint32_t a) {
    asm volatile("ldmatrix.sync.aligned.m8n8.x4.trans.shared.b16 {%0,%1,%2,%3}, [%4];"
                 : "=r"(r[0]), "=r"(r[1]), "=r"(r[2]), "=r"(r[3]) : "r"(a));
}
__device__ __forceinline__ void mma16816(float* c, const uint32_t* a,
                                         uint32_t b0, uint32_t b1) {
    asm volatile(
        "mma.sync.aligned.m16n8k16.row.col.f32.bf16.bf16.f32 "
        "{%0,%1,%2,%3}, {%4,%5,%6,%7}, {%8,%9}, {%0,%1,%2,%3};"
        : "+f"(c[0]), "+f"(c[1]), "+f"(c[2]), "+f"(c[3])
        : "r"(a[0]), "r"(a[1]), "r"(a[2]), "r"(a[3]), "r"(b0), "r"(b1));
}

#define BAR_SYNC(id, n)   asm volatile("bar.sync %0, %1;"   :: "r"(id), "r"(n) : "memory")
#define BAR_ARRIVE(id, n) asm volatile("bar.arrive %0, %1;" :: "r"(id), "r"(n) : "memory")
// ids: FULL = 1 + (t&1), EMPTY = 3 + (t&1), PROD = 5

// ---------------- B split precompute (scaled by 1/m, exact pow2) ----------------
__global__ void split_b_kernel(const float* __restrict__ W0, const float* __restrict__ W1,
                               const float* __restrict__ W2, const float* __restrict__ W3)
{
    int idx = blockIdx.x * blockDim.x + threadIdx.x;
    if (idx >= 43520) return;
    int e = idx * 2;
    const float* src; int off; float sc;
    if (e < 65536)      { src = W0; off = e;         sc = 1.0f / 256.0f; }
    else if (e < 81920) { src = W1; off = e - 65536; sc = 1.0f / 128.0f; }
    else if (e < 86016) { src = W2; off = e - 81920; sc = 1.0f / 64.0f; }
    else                { src = W3; off = e - 86016; sc = 1.0f / 32.0f; }
    float2 v = *reinterpret_cast<const float2*>(src + off);
    uint32_t h, l;
    split2(v.x * sc, v.y * sc, h, l);
    reinterpret_cast<uint32_t*>(g_bsplit)[idx] = h;
    reinterpret_cast<uint32_t*>(g_bsplit)[43520 + idx] = l;
}

// ---------------- one irrep-block GEMM (device) ----------------
template<int D, int M, int ROWS, int NU, int WR, int WC>
__device__ __forceinline__
void run_mma(char* sm,
             const float* __restrict__ x, const float* __restrict__ wt,
             float* __restrict__ out, int n0, int nrows, int xo, int wo, int moff)
{
    constexpr int BK  = 16;
    constexpr int SA  = BK + 8;              // bf16
    constexpr int SB  = M + 8;               // bf16
    constexpr int KT  = M / BK;
    constexpr int TR  = ROWS / WR, TC = M / WC;
    constexpr int MR  = TR / 16,   MC = TC / 8;
    static_assert(WR * WC == 8 && MR >= 1 && (MC % 2) == 0, "warp grid");
    constexpr int XROW = BK * D + 4;         // floats
    constexpr int WROW = BK + 4;             // floats

    // rings: As x2 (full/empty), Bs x4, raw X/W x3
    constexpr uint32_t PS_A   = (uint32_t)ROWS * SA * 2u;
    constexpr uint32_t A_SLOT = 2u * PS_A;
    constexpr uint32_t AS_BYTES = 2u * A_SLOT;
    constexpr uint32_t BPLANE = (uint32_t)BK * SB * 2u;
    constexpr uint32_t B_SLOT = 2u * BPLANE;
    constexpr uint32_t BS_BYTES = 4u * B_SLOT;
    constexpr uint32_t X_SLOT = (uint32_t)NU * XROW * 4u;
    constexpr uint32_t W_SLOT = (uint32_t)NU * WROW * 4u;

    const uint32_t smA = (uint32_t)__cvta_generic_to_shared(sm);
    const uint32_t smB = smA + AS_BYTES;
    const uint32_t smX = smB + BS_BYTES;
    const uint32_t smW = smX + 3u * X_SLOT;

    typedef __nv_bfloat16 bf;
    bf*    As  = reinterpret_cast<bf*>(sm);
    float* Xs  = reinterpret_cast<float*>(sm + (smX - smA));
    float* Wsm = reinterpret_cast<float*>(sm + (smW - smA));

    const int tid = threadIdx.x, lane = tid & 31;

    if (tid < 256) {
        // ======================= CONSUMERS (8 warps) =======================
        const int wid = tid >> 5;
        const int warpR = wid % WR, warpC = wid / WR;
        const int rw0 = warpR * TR, c0w = warpC * TC;

        const uint32_t aAddr0 = smA +
            (uint32_t)(((rw0 + (lane & 15)) * SA + ((lane >> 4) << 3)) * 2);
        const int bg = lane >> 3;
        const uint32_t bAddr0 = smB +
            (uint32_t)(((((bg & 1) << 3) + (lane & 7)) * SB + c0w + ((bg >> 1) << 3)) * 2);

        float acc[MR][MC][4];
#pragma unroll
        for (int a = 0; a < MR; ++a)
#pragma unroll
            for (int b = 0; b < MC; ++b)
#pragma unroll
                for (int c = 0; c < 4; ++c) acc[a][b][c] = 0.0f;

#pragma unroll 1
        for (int t = 0; t < KT; ++t) {
            BAR_SYNC(1 + (t & 1), 384);
            const uint32_t aBase = aAddr0 + (uint32_t)(t & 1) * A_SLOT;
            const uint32_t bBase = bAddr0 + (uint32_t)(t & 3) * B_SLOT;
            uint32_t ah[MR][4], al[MR][4];
#pragma unroll
            for (int mr = 0; mr < MR; ++mr) {
                uint32_t a = aBase + (uint32_t)(mr * 16 * SA * 2);
                ldsm4(ah[mr], a);
                ldsm4(al[mr], a + PS_A);
            }
#pragma unroll
            for (int mc2 = 0; mc2 < MC / 2; ++mc2) {
                uint32_t b = bBase + (uint32_t)(mc2 * 32);
                uint32_t bh[4], bl[4];
                ldsm4t(bh, b);
                ldsm4t(bl, b + BPLANE);
#pragma unroll
                for (int mr = 0; mr < MR; ++mr) {
                    mma16816(acc[mr][2 * mc2],     ah[mr], bh[0], bh[1]);
                    mma16816(acc[mr][2 * mc2 + 1], ah[mr], bh[2], bh[3]);
                }
#pragma unroll
                for (int mr = 0; mr < MR; ++mr) {
                    mma16816(acc[mr][2 * mc2],     ah[mr], bl[0], bl[1]);
                    mma16816(acc[mr][2 * mc2 + 1], ah[mr], bl[2], bl[3]);
                }
#pragma unroll
                for (int mr = 0; mr < MR; ++mr) {
                    mma16816(acc[mr][2 * mc2],     al[mr], bh[0], bh[1]);
                    mma16816(acc[mr][2 * mc2 + 1], al[mr], bh[2], bh[3]);
                }
            }
            if (t < KT - 2) BAR_ARRIVE(3 + (t & 1), 384);
        }

        // ---- epilogue ----
#pragma unroll
        for (int mr = 0; mr < MR; ++mr) {
#pragma unroll
            for (int half = 0; half < 2; ++half) {
                const int r = rw0 + mr * 16 + (lane >> 2) + half * 8;
                if (r < NU * D) {
                    const int nl = r / D, i = r - nl * D;
                    const int n = n0 + nl;
                    if (n < nrows) {
                        float* orow = out + (size_t)n * DIM_ + xo;
#pragma unroll
                        for (int mc = 0; mc < MC; ++mc) {
                            const int cw = c0w + mc * 8 + 2 * (lane & 3);
                            const float v0 = acc[mr][mc][half * 2];
                            const float v1 = acc[mr][mc][half * 2 + 1];
                            if constexpr (D == 1) {
                                *reinterpret_cast<float2*>(orow + cw) =
                                    make_float2(v0, v1);
                            } else {
                                orow[(size_t)cw * D + i]       = v0;
                                orow[(size_t)(cw + 1) * D + i] = v1;
                            }
                        }
                    }
                }
            }
        }
    } else {
        // ======================= PRODUCERS (4 warps) =======================
        const int ptid = tid - 256;
        constexpr int PT  = 128 / ROWS;      // fill threads per row (>=1)
        static_assert(PT * ROWS == 128, "producer rows");
        constexpr int EPT = BK / PT;
        constexpr int NP  = EPT / 2;
        static_assert(EPT % 4 == 0, "wt vec4");

        const int rfill = ptid / PT;
        const int kbase = (ptid % PT) * EPT;
        const int nl_f = rfill / D, i_f = rfill - nl_f * D;
        const bool fvalid = (rfill < NU * D) && ((n0 + nl_f) < nrows);

        // hoisted cp.async chunk descriptors over 128 producer threads
        constexpr int BCH = 2 * BK * (M / 8);
        constexpr int NBC = (BCH + 127) / 128;
        constexpr int XCHR = BK * D / 4;
        constexpr int XCH = NU * XCHR;
        constexpr int NXC = (XCH + 127) / 128;
        constexpr int WCH = NU * (BK / 4);
        constexpr int NWC = (WCH + 127) / 128;

        const char* bsrcp[NBC]; uint32_t bdsto[NBC]; bool bokk[NBC];
        {
            const char* gb = reinterpret_cast<const char*>(g_bsplit);
#pragma unroll
            for (int i = 0; i < NBC; ++i) {
                int c = ptid + i * 128;
                bokk[i] = (c < BCH);
                int cc = bokk[i] ? c : 0;
                int plane = cc / (BK * (M / 8));
                int rem   = cc - plane * (BK * (M / 8));
                int k     = rem / (M / 8);
                int sg    = rem - k * (M / 8);
                bdsto[i] = smB + (uint32_t)plane * BPLANE
                         + (uint32_t)((k * SB + sg * 8) * 2);
                bsrcp[i] = gb + (size_t)(plane * 87040 + moff + k * M + sg * 8) * 2;
            }
        }
        const float* xsrcp[NXC]; uint32_t xdsto[NXC]; bool xokk[NXC];
        {
#pragma unroll
            for (int i = 0; i < NXC; ++i) {
                int c = ptid + i * 128;
                bool ok = (c < XCH);
                int cc = ok ? c : 0;
                int row = cc / XCHR, sg = cc - row * XCHR;
                xokk[i] = ok && ((n0 + row) < nrows);
                xdsto[i] = smX + (uint32_t)((row * XROW + sg * 4) * 4);
                xsrcp[i] = x + (size_t)(n0 + row) * DIM_ + xo + sg * 4;
            }
        }
        const float* wsrcp[NWC]; uint32_t wdsto[NWC]; bool wokk[NWC];
        {
#pragma unroll
            for (int i = 0; i < NWC; ++i) {
                int c = ptid + i * 128;
                bool ok = (c < WCH);
                int cc = ok ? c : 0;
                int row = cc / (BK / 4), sg = cc - row * (BK / 4);
                wokk[i] = ok && ((n0 + row) < nrows);
                wdsto[i] = smW + (uint32_t)((row * WROW + sg * 4) * 4);
                wsrcp[i] = wt + (size_t)(n0 + row) * WNUM_ + wo + sg * 4;
            }
        }

        auto issue_tile = [&](int t) {
            const uint32_t so_b = (uint32_t)(t & 3) * B_SLOT;
            const uint32_t so_x = (uint32_t)(t % 3) * X_SLOT;
            const uint32_t so_w = (uint32_t)(t % 3) * W_SLOT;
#pragma unroll
            for (int i = 0; i < NBC; ++i) {
                if (bokk[i]) cp_async16(bdsto[i] + so_b, bsrcp[i]);
                bsrcp[i] += (size_t)BK * M * 2;
            }
#pragma unroll
            for (int i = 0; i < NXC; ++i) {
                if (xokk[i]) cp_async16(xdsto[i] + so_x, xsrcp[i]);
                xsrcp[i] += BK * D;
            }
#pragma unroll
            for (int i = 0; i < NWC; ++i) {
                if (wokk[i]) cp_async16(wdsto[i] + so_w, wsrcp[i]);
                wsrcp[i] += BK;
            }
        };

        auto split_tile = [&](int t) {
            const int slot = t % 3;
            uint32_t hh[NP], ll[NP];
            if (fvalid) {
                const float* xr = Xs + (size_t)slot * (NU * XROW) + nl_f * XROW + i_f;
                const float* wr = Wsm + (size_t)slot * (NU * WROW) + nl_f * WROW + kbase;
                if constexpr (D == 1) {
#pragma unroll
                    for (int v = 0; v < EPT / 4; ++v) {
                        float4 xv = *reinterpret_cast<const float4*>(xr + kbase + 4 * v);
                        float4 wv = *reinterpret_cast<const float4*>(wr + 4 * v);
                        split2(xv.x * wv.x, xv.y * wv.y, hh[2 * v],     ll[2 * v]);
                        split2(xv.z * wv.z, xv.w * wv.w, hh[2 * v + 1], ll[2 * v + 1]);
                    }
                } else {
                    alignas(16) float w[EPT];
#pragma unroll
                    for (int v = 0; v < EPT / 4; ++v)
                        reinterpret_cast<float4*>(w)[v] =
                            *reinterpret_cast<const float4*>(wr + 4 * v);
#pragma unroll
                    for (int p = 0; p < NP; ++p) {
                        float s0 = xr[(kbase + 2 * p) * D]     * w[2 * p];
                        float s1 = xr[(kbase + 2 * p + 1) * D] * w[2 * p + 1];
                        split2(s0, s1, hh[p], ll[p]);
                    }
                }
            } else {
#pragma unroll
                for (int p = 0; p < NP; ++p) { hh[p] = 0; ll[p] = 0; }
            }
            const uint32_t aOff = (uint32_t)(t & 1) * A_SLOT;
            ull* dh = reinterpret_cast<ull*>(
                reinterpret_cast<char*>(As) + aOff + (rfill * SA + kbase) * 2);
            ull* dl = reinterpret_cast<ull*>(
                reinterpret_cast<char*>(As) + aOff + PS_A + (rfill * SA + kbase) * 2);
#pragma unroll
            for (int q = 0; q < NP / 2; ++q) {
                dh[q] = (ull)hh[2 * q] | ((ull)hh[2 * q + 1] << 32);
                dl[q] = (ull)ll[2 * q] | ((ull)ll[2 * q + 1] << 32);
            }
        };

        // prologue: 2 tiles in flight
        issue_tile(0); cp_commit();
        if (1 < KT) issue_tile(1);
        cp_commit();

#pragma unroll 1
        for (int t = 0; t < KT; ++t) {
            cp_wait1();
            BAR_SYNC(5, 128);               // raw(t) visible; raw ring reuse safe
            if (t >= 2) BAR_SYNC(3 + (t & 1), 384);   // As/Bs slot free
            split_tile(t);
            BAR_ARRIVE(1 + (t & 1), 384);   // full
            if (t + 2 < KT) issue_tile(t + 2);
            cp_commit();
        }
    }
}

// ---------------- fused dispatch ----------------
#define CHUNK_CTAS 229
#define CHUNK_ROWS 1600
#define SMEM_DYN 110592

__global__ __launch_bounds__(384, 1)
void tp_mma_fused(const float* __restrict__ x, const float* __restrict__ wt,
                  float* __restrict__ out, int nrows)
{
    extern __shared__ __align__(16) char smraw[];
    const int bid = blockIdx.x;
    const int r = bid / CHUNK_CTAS;
    const int q = bid - r * CHUNK_CTAS;
    const int base = r * CHUNK_ROWS;

    if (q < 25) {
        run_mma<1, 256, 64, 64, 2, 4>(smraw, x, wt, out,
                                      base + q * 64, nrows, 0, 0, 0);
    } else if (q < 65) {
        run_mma<3, 128, 128, 40, 4, 2>(smraw, x, wt, out,
                                       base + (q - 25) * 40, nrows, 256, 256, 65536);
    } else if (q < 129) {
        run_mma<5, 64, 128, 25, 4, 2>(smraw, x, wt, out,
                                      base + (q - 65) * 25, nrows, 640, 384, 81920);
    } else {
        run_mma<7, 32, 128, 16, 8, 1>(smraw, x, wt, out,
                                      base + (q - 129) * 16, nrows, 960, 448, 86016);
    }
}

// ---------------- launch ----------------
extern "C" void kernel_launch(void* const* d_in, const int* in_sizes, int n_in,
                              void* d_out, int out_size)
{
    const float* x  = (const float*)d_in[0];
    const float* wtp = (const float*)d_in[1];
    const float* W0 = (const float*)d_in[2];
    const float* W1 = (const float*)d_in[3];
    const float* W2 = (const float*)d_in[4];
    const float* W3 = (const float*)d_in[5];
    float* out = (float*)d_out;

    const int nrows = in_sizes[0] / DIM_;

    static int attr_set = 0;
    if (!attr_set) {
        cudaFuncSetAttribute(tp_mma_fused,
                             cudaFuncAttributeMaxDynamicSharedMemorySize, SMEM_DYN);
        attr_set = 1;
    }

    split_b_kernel<<<170, 256>>>(W0, W1, W2, W3);

    const int nchunk = (nrows + CHUNK_ROWS - 1) / CHUNK_ROWS;
    tp_mma_fused<<<nchunk * CHUNK_CTAS, 384, SMEM_DYN>>>(x, wtp, out, nrows);
}

// round 15
// speedup vs baseline: 1.3730x; 1.3730x over previous
#include <cuda_runtime.h>
#include <cuda_bf16.h>
#include <cstdint>

// out[n,w,i] = (1/m) * sum_u x[n,u,i] * weight[n,u] * W[u,w]
// Irreps: 256x0e + 128x1o + 64x2e + 32x3o ; DIM=1184, WNUM=480
// R15: homogeneous warps, ONE barrier per k-tile; split(t+1) shares the
//      window with compute(t) (warps destagger). B ring 4, raw ring 3.

#define DIM_ 1184
#define WNUM_ 480
typedef unsigned long long ull;

__device__ __align__(16) __nv_bfloat16 g_bsplit[2 * 87040];

__device__ __forceinline__ void split2(float s0, float s1, uint32_t& h, uint32_t& l) {
    asm("cvt.rn.satfinite.bf16x2.f32 %0, %1, %2;" : "=r"(h) : "f"(s1), "f"(s0));
    float h0 = __uint_as_float(h << 16);
    float h1 = __uint_as_float(h & 0xffff0000u);
    asm("cvt.rn.satfinite.bf16x2.f32 %0, %1, %2;" : "=r"(l) : "f"(s1 - h1), "f"(s0 - h0));
}

__device__ __forceinline__ void cp_async16(uint32_t dst, const void* src) {
    asm volatile("cp.async.cg.shared.global [%0], [%1], 16;" :: "r"(dst), "l"(src));
}
__device__ __forceinline__ void cp_commit() { asm volatile("cp.async.commit_group;"); }
__device__ __forceinline__ void cp_wait1()  { asm volatile("cp.async.wait_group 1;" ::: "memory"); }

__device__ __forceinline__ void ldsm4(uint32_t* r, uint32_t a) {
    asm volatile("ldmatrix.sync.aligned.m8n8.x4.shared.b16 {%0,%1,%2,%3}, [%4];"
                 : "=r"(r[0]), "=r"(r[1]), "=r"(r[2]), "=r"(r[3]) : "r"(a));
}
__device__ __forceinline__ void ldsm4t(uint32_t* r, uint32_t a) {
    asm volatile("ldmatrix.sync.aligned.m8n8.x4.trans.shared.b16 {%0,%1,%2,%3}, [%4];"
                 : "=r"(r[0]), "=r"(r[1]), "=r"(r[2]), "=r"(r[3]) : "r"(a));
}
__device__ __forceinline__ void mma16816(float* c, const uint32_t* a,
                                         uint32_t b0, uint32_t b1) {
    asm volatile(
        "mma.sync.aligned.m16n8k16.row.col.f32.bf16.bf16.f32 "
        "{%0,%1,%2,%3}, {%4,%5,%6,%7}, {%8,%9}, {%0,%1,%2,%3};"
        : "+f"(c[0]), "+f"(c[1]), "+f"(c[2]), "+f"(c[3])
        : "r"(a[0]), "r"(a[1]), "r"(a[2]), "r"(a[3]), "r"(b0), "r"(b1));
}

// ---------------- B split precompute (scaled by 1/m, exact pow2) ----------------
__global__ void split_b_kernel(const float* __restrict__ W0, const float* __restrict__ W1,
                               const float* __restrict__ W2, const float* __restrict__ W3)
{
    int idx = blockIdx.x * blockDim.x + threadIdx.x;
    if (idx >= 43520) return;
    int e = idx * 2;
    const float* src; int off; float sc;
    if (e < 65536)      { src = W0; off = e;         sc = 1.0f / 256.0f; }
    else if (e < 81920) { src = W1; off = e - 65536; sc = 1.0f / 128.0f; }
    else if (e < 86016) { src = W2; off = e - 81920; sc = 1.0f / 64.0f; }
    else                { src = W3; off = e - 86016; sc = 1.0f / 32.0f; }
    float2 v = *reinterpret_cast<const float2*>(src + off);
    uint32_t h, l;
    split2(v.x * sc, v.y * sc, h, l);
    reinterpret_cast<uint32_t*>(g_bsplit)[idx] = h;
    reinterpret_cast<uint32_t*>(g_bsplit)[43520 + idx] = l;
}

// ---------------- one irrep-block GEMM (device) ----------------
template<int D, int M, int ROWS, int NU, int WR, int WC>
__device__ __forceinline__
void run_mma(char* sm,
             const float* __restrict__ x, const float* __restrict__ wt,
             float* __restrict__ out, int n0, int nrows, int xo, int wo, int moff)
{
    constexpr int BK  = 16;
    constexpr int SA  = BK + 8;
    constexpr int SB  = M + 8;
    constexpr int KT  = M / BK;
    constexpr int TR  = ROWS / WR, TC = M / WC;
    constexpr int MR  = TR / 16,   MC = TC / 8;
    static_assert(WR * WC == 8 && MR >= 1 && (MC % 2) == 0, "warp grid");
    constexpr int PT  = 256 / ROWS;
    constexpr int EPT = BK / PT;
    constexpr int NP  = EPT / 2;
    static_assert(EPT % 4 == 0, "wt vec4");
    constexpr int XROW = BK * D + 4;
    constexpr int WROW = BK + 4;

    // rings: As x2 (2 planes each), Bs x4 (2 planes), raw X/W x3
    constexpr uint32_t PS_A   = (uint32_t)ROWS * SA * 2u;
    constexpr uint32_t A_SLOT = 2u * PS_A;
    constexpr uint32_t AS_BYTES = 2u * A_SLOT;
    constexpr uint32_t BPLANE = (uint32_t)BK * SB * 2u;
    constexpr uint32_t B_SLOT = 2u * BPLANE;
    constexpr uint32_t BS_BYTES = 4u * B_SLOT;
    constexpr uint32_t X_SLOT = (uint32_t)NU * XROW * 4u;
    constexpr uint32_t W_SLOT = (uint32_t)NU * WROW * 4u;

    const uint32_t smA = (uint32_t)__cvta_generic_to_shared(sm);
    const uint32_t smB = smA + AS_BYTES;
    const uint32_t smX = smB + BS_BYTES;
    const uint32_t smW = smX + 3u * X_SLOT;

    typedef __nv_bfloat16 bf;
    bf*    As  = reinterpret_cast<bf*>(sm);
    float* Xs  = reinterpret_cast<float*>(sm + (smX - smA));
    float* Wsm = reinterpret_cast<float*>(sm + (smW - smA));

    const int tid = threadIdx.x, lane = tid & 31, wid = tid >> 5;
    const int warpR = wid % WR, warpC = wid / WR;
    const int rw0 = warpR * TR, c0w = warpC * TC;

    const int rfill = tid / PT;
    const int kbase = (tid % PT) * EPT;
    const int nl_f = rfill / D, i_f = rfill - nl_f * D;
    const bool fvalid = (rfill < NU * D) && ((n0 + nl_f) < nrows);

    const uint32_t aAddr0 = smA +
        (uint32_t)(((rw0 + (lane & 15)) * SA + ((lane >> 4) << 3)) * 2);
    const int bg = lane >> 3;
    const uint32_t bAddr0 = smB +
        (uint32_t)(((((bg & 1) << 3) + (lane & 7)) * SB + c0w + ((bg >> 1) << 3)) * 2);

    // ---- hoisted cp.async chunk descriptors ----
    constexpr int BCH = 2 * BK * (M / 8);
    constexpr int NBC = (BCH + 255) / 256;
    constexpr int XCHR = BK * D / 4;
    constexpr int XCH = NU * XCHR;
    constexpr int NXC = (XCH + 255) / 256;
    constexpr int WCH = NU * (BK / 4);
    constexpr int NWC = 1;

    const char* bsrcp[NBC]; uint32_t bdsto[NBC]; bool bokk[NBC];
    {
        const char* gb = reinterpret_cast<const char*>(g_bsplit);
#pragma unroll
        for (int i = 0; i < NBC; ++i) {
            int c = tid + i * 256;
            bokk[i] = (c < BCH);
            int cc = bokk[i] ? c : 0;
            int plane = cc / (BK * (M / 8));
            int rem   = cc - plane * (BK * (M / 8));
            int k     = rem / (M / 8);
            int sg    = rem - k * (M / 8);
            bdsto[i] = smB + (uint32_t)plane * BPLANE + (uint32_t)((k * SB + sg * 8) * 2);
            bsrcp[i] = gb + (size_t)(plane * 87040 + moff + k * M + sg * 8) * 2;
        }
    }
    const float* xsrcp[NXC]; uint32_t xdsto[NXC]; bool xokk[NXC];
    {
#pragma unroll
        for (int i = 0; i < NXC; ++i) {
            int c = tid + i * 256;
            bool ok = (c < XCH);
            int cc = ok ? c : 0;
            int row = cc / XCHR, sg = cc - row * XCHR;
            xokk[i] = ok && ((n0 + row) < nrows);
            xdsto[i] = smX + (uint32_t)((row * XROW + sg * 4) * 4);
            xsrcp[i] = x + (size_t)(n0 + row) * DIM_ + xo + sg * 4;
        }
    }
    const float* wsrcp[NWC]; uint32_t wdsto[NWC]; bool wokk[NWC];
    {
#pragma unroll
        for (int i = 0; i < NWC; ++i) {
            int c = tid + i * 256;
            bool ok = (c < WCH);
            int cc = ok ? c : 0;
            int row = cc / (BK / 4), sg = cc - row * (BK / 4);
            wokk[i] = ok && ((n0 + row) < nrows);
            wdsto[i] = smW + (uint32_t)((row * WROW + sg * 4) * 4);
            wsrcp[i] = wt + (size_t)(n0 + row) * WNUM_ + wo + sg * 4;
        }
    }

    float acc[MR][MC][4];
#pragma unroll
    for (int a = 0; a < MR; ++a)
#pragma unroll
        for (int b = 0; b < MC; ++b)
#pragma unroll
            for (int c = 0; c < 4; ++c) acc[a][b][c] = 0.0f;

    auto issue_tile = [&](int t) {
        const uint32_t so_b = (uint32_t)(t & 3) * B_SLOT;
        const uint32_t so_x = (uint32_t)(t % 3) * X_SLOT;
        const uint32_t so_w = (uint32_t)(t % 3) * W_SLOT;
#pragma unroll
        for (int i = 0; i < NBC; ++i) {
            if (bokk[i]) cp_async16(bdsto[i] + so_b, bsrcp[i]);
            bsrcp[i] += (size_t)BK * M * 2;
        }
#pragma unroll
        for (int i = 0; i < NXC; ++i) {
            if (xokk[i]) cp_async16(xdsto[i] + so_x, xsrcp[i]);
            xsrcp[i] += BK * D;
        }
#pragma unroll
        for (int i = 0; i < NWC; ++i) {
            if (wokk[i]) cp_async16(wdsto[i] + so_w, wsrcp[i]);
            wsrcp[i] += BK;
        }
    };

    auto split_tile = [&](int t) {
        const int slot = t % 3;
        uint32_t hh[NP], ll[NP];
        if (fvalid) {
            const float* xr = Xs + (size_t)slot * (NU * XROW) + nl_f * XROW + i_f;
            const float* wr = Wsm + (size_t)slot * (NU * WROW) + nl_f * WROW + kbase;
            if constexpr (D == 1) {
#pragma unroll
                for (int v = 0; v < EPT / 4; ++v) {
                    float4 xv = *reinterpret_cast<const float4*>(xr + kbase + 4 * v);
                    float4 wv = *reinterpret_cast<const float4*>(wr + 4 * v);
                    split2(xv.x * wv.x, xv.y * wv.y, hh[2 * v],     ll[2 * v]);
                    split2(xv.z * wv.z, xv.w * wv.w, hh[2 * v + 1], ll[2 * v + 1]);
                }
            } else {
                alignas(16) float w[EPT];
#pragma unroll
                for (int v = 0; v < EPT / 4; ++v)
                    reinterpret_cast<float4*>(w)[v] =
                        *reinterpret_cast<const float4*>(wr + 4 * v);
#pragma unroll
                for (int p = 0; p < NP; ++p) {
                    float s0 = xr[(kbase + 2 * p) * D]     * w[2 * p];
                    float s1 = xr[(kbase + 2 * p + 1) * D] * w[2 * p + 1];
                    split2(s0, s1, hh[p], ll[p]);
                }
            }
        } else {
#pragma unroll
            for (int p = 0; p < NP; ++p) { hh[p] = 0; ll[p] = 0; }
        }
        const uint32_t aOff = (uint32_t)(t & 1) * A_SLOT;
        ull* dh = reinterpret_cast<ull*>(
            reinterpret_cast<char*>(As) + aOff + (rfill * SA + kbase) * 2);
        ull* dl = reinterpret_cast<ull*>(
            reinterpret_cast<char*>(As) + aOff + PS_A + (rfill * SA + kbase) * 2);
#pragma unroll
        for (int q = 0; q < NP / 2; ++q) {
            dh[q] = (ull)hh[2 * q] | ((ull)hh[2 * q + 1] << 32);
            dl[q] = (ull)ll[2 * q] | ((ull)ll[2 * q + 1] << 32);
        }
    };

    // ---- prologue: 2 tiles in flight, split tile 0 ----
    issue_tile(0); cp_commit();
    if (KT > 1) issue_tile(1);
    cp_commit();
    cp_wait1();            // g0 complete
    __syncthreads();       // g0 visible to all
    split_tile(0);         // As[0]

    uint32_t ah[MR][4], al[MR][4];

#pragma unroll 1
    for (int t = 0; t < KT; ++t) {
        if (t + 2 < KT) issue_tile(t + 2);
        cp_commit();
        cp_wait1();            // g_{t+1} complete (own groups)
        __syncthreads();       // publishes: split(t) STS, raw(t+1), Bs(t+1)

        // ---- ldsm A(t) fragments ----
        const uint32_t aBase = aAddr0 + (uint32_t)(t & 1) * A_SLOT;
#pragma unroll
        for (int mr = 0; mr < MR; ++mr) {
            uint32_t a = aBase + (uint32_t)(mr * 16 * SA * 2);
            ldsm4(ah[mr], a);
            ldsm4(al[mr], a + PS_A);
        }

        // ---- compute(t): B slot t&3 ----
        const uint32_t bBase = bAddr0 + (uint32_t)(t & 3) * B_SLOT;
#pragma unroll
        for (int mc2 = 0; mc2 < MC / 2; ++mc2) {
            uint32_t b = bBase + (uint32_t)(mc2 * 32);
            uint32_t bh[4], bl[4];
            ldsm4t(bh, b);
            ldsm4t(bl, b + BPLANE);
#pragma unroll
            for (int mr = 0; mr < MR; ++mr) {
                mma16816(acc[mr][2 * mc2],     ah[mr], bh[0], bh[1]);
                mma16816(acc[mr][2 * mc2 + 1], ah[mr], bh[2], bh[3]);
            }
#pragma unroll
            for (int mr = 0; mr < MR; ++mr) {
                mma16816(acc[mr][2 * mc2],     ah[mr], bl[0], bl[1]);
                mma16816(acc[mr][2 * mc2 + 1], ah[mr], bl[2], bl[3]);
            }
#pragma unroll
            for (int mr = 0; mr < MR; ++mr) {
                mma16816(acc[mr][2 * mc2],     al[mr], bh[0], bh[1]);
                mma16816(acc[mr][2 * mc2 + 1], al[mr], bh[2], bh[3]);
            }
        }

        // ---- split(t+1): same barrier window, destaggered across warps ----
        if (t + 1 < KT) split_tile(t + 1);
    }

    // ---- epilogue ----
#pragma unroll
    for (int mr = 0; mr < MR; ++mr) {
#pragma unroll
        for (int half = 0; half < 2; ++half) {
            const int r = rw0 + mr * 16 + (lane >> 2) + half * 8;
            if (r < NU * D) {
                const int nl = r / D, i = r - nl * D;
                const int n = n0 + nl;
                if (n < nrows) {
                    float* orow = out + (size_t)n * DIM_ + xo;
#pragma unroll
                    for (int mc = 0; mc < MC; ++mc) {
                        const int cw = c0w + mc * 8 + 2 * (lane & 3);
                        const float v0 = acc[mr][mc][half * 2];
                        const float v1 = acc[mr][mc][half * 2 + 1];
                        if constexpr (D == 1) {
                            *reinterpret_cast<float2*>(orow + cw) = make_float2(v0, v1);
                        } else {
                            orow[(size_t)cw * D + i]       = v0;
                            orow[(size_t)(cw + 1) * D + i] = v1;
                        }
                    }
                }
            }
        }
    }
}

// ---------------- fused dispatch ----------------
#define CHUNK_CTAS 229
#define CHUNK_ROWS 1600
#define SMEM_DYN 110592

__global__ __launch_bounds__(256, 2)
void tp_mma_fused(const float* __restrict__ x, const float* __restrict__ wt,
                  float* __restrict__ out, int nrows)
{
    extern __shared__ __align__(16) char smraw[];
    const int bid = blockIdx.x;
    const int r = bid / CHUNK_CTAS;
    const int q = bid - r * CHUNK_CTAS;
    const int base = r * CHUNK_ROWS;

    if (q < 25) {
        run_mma<1, 256, 64, 64, 2, 4>(smraw, x, wt, out,
                                      base + q * 64, nrows, 0, 0, 0);
    } else if (q < 65) {
        run_mma<3, 128, 128, 40, 4, 2>(smraw, x, wt, out,
                                       base + (q - 25) * 40, nrows, 256, 256, 65536);
    } else if (q < 129) {
        run_mma<5, 64, 128, 25, 4, 2>(smraw, x, wt, out,
                                      base + (q - 65) * 25, nrows, 640, 384, 81920);
    } else {
        run_mma<7, 32, 128, 16, 8, 1>(smraw, x, wt, out,
                                      base + (q - 129) * 16, nrows, 960, 448, 86016);
    }
}

// ---------------- launch ----------------
extern "C" void kernel_launch(void* const* d_in, const int* in_sizes, int n_in,
                              void* d_out, int out_size)
{
    const float* x  = (const float*)d_in[0];
    const float* wtp = (const float*)d_in[1];
    const float* W0 = (const float*)d_in[2];
    const float* W1 = (const float*)d_in[3];
    const float* W2 = (const float*)d_in[4];
    const float* W3 = (const float*)d_in[5];
    float* out = (float*)d_out;

    const int nrows = in_sizes[0] / DIM_;

    static int attr_set = 0;
    if (!attr_set) {
        cudaFuncSetAttribute(tp_mma_fused,
                             cudaFuncAttributeMaxDynamicSharedMemorySize, SMEM_DYN);
        attr_set = 1;
    }

    split_b_kernel<<<170, 256>>>(W0, W1, W2, W3);

    const int nchunk = (nrows + CHUNK_ROWS - 1) / CHUNK_ROWS;
    tp_mma_fused<<<nchunk * CHUNK_CTAS, 256, SMEM_DYN>>>(x, wtp, out, nrows);
}

// round 16
// speedup vs baseline: 1.5478x; 1.1273x over previous
#include <cuda_runtime.h>
#include <cuda_fp16.h>
#include <cstdint>

// out[n,w,i] = (1/m) * sum_u x[n,u,i] * weight[n,u] * W[u,w]
// Irreps: 256x0e + 128x1o + 64x2e + 32x3o ; DIM=1184, WNUM=480
// R16: fp16 2-term split. S = Sh+Sl (two fp16 planes, ~2^-23 exact);
//      W single fp16 plane (error 2^-12 -> rel_err ~1.5e-4).
//      mma count -33%, B traffic/ldsm -50% vs R15.

#define DIM_ 1184
#define WNUM_ 480
typedef unsigned long long ull;

// single fp16 plane of W (scaled by 1/m, exact pow2)
__device__ __align__(16) __half g_bh[87040];

__device__ __forceinline__ void split2h(float s0, float s1, uint32_t& h, uint32_t& l) {
    asm("cvt.rn.f16x2.f32 %0, %1, %2;" : "=r"(h) : "f"(s1), "f"(s0));
    float h0, h1;
    asm("{\n\t.reg .f16 a, b;\n\tmov.b32 {a, b}, %2;\n\t"
        "cvt.f32.f16 %0, a;\n\tcvt.f32.f16 %1, b;\n\t}"
        : "=f"(h0), "=f"(h1) : "r"(h));
    asm("cvt.rn.f16x2.f32 %0, %1, %2;" : "=r"(l) : "f"(s1 - h1), "f"(s0 - h0));
}

__device__ __forceinline__ void cp_async16(uint32_t dst, const void* src) {
    asm volatile("cp.async.cg.shared.global [%0], [%1], 16;" :: "r"(dst), "l"(src));
}
__device__ __forceinline__ void cp_commit() { asm volatile("cp.async.commit_group;"); }
__device__ __forceinline__ void cp_wait1()  { asm volatile("cp.async.wait_group 1;" ::: "memory"); }

__device__ __forceinline__ void ldsm4(uint32_t* r, uint32_t a) {
    asm volatile("ldmatrix.sync.aligned.m8n8.x4.shared.b16 {%0,%1,%2,%3}, [%4];"
                 : "=r"(r[0]), "=r"(r[1]), "=r"(r[2]), "=r"(r[3]) : "r"(a));
}
__device__ __forceinline__ void ldsm4t(uint32_t* r, uint32_t a) {
    asm volatile("ldmatrix.sync.aligned.m8n8.x4.trans.shared.b16 {%0,%1,%2,%3}, [%4];"
                 : "=r"(r[0]), "=r"(r[1]), "=r"(r[2]), "=r"(r[3]) : "r"(a));
}
__device__ __forceinline__ void mma16816h(float* c, const uint32_t* a,
                                          uint32_t b0, uint32_t b1) {
    asm volatile(
        "mma.sync.aligned.m16n8k16.row.col.f32.f16.f16.f32 "
        "{%0,%1,%2,%3}, {%4,%5,%6,%7}, {%8,%9}, {%0,%1,%2,%3};"
        : "+f"(c[0]), "+f"(c[1]), "+f"(c[2]), "+f"(c[3])
        : "r"(a[0]), "r"(a[1]), "r"(a[2]), "r"(a[3]), "r"(b0), "r"(b1));
}

// ---------------- B precompute: fp16, scaled by 1/m (exact pow2) ----------------
__global__ void split_b_kernel(const float* __restrict__ W0, const float* __restrict__ W1,
                               const float* __restrict__ W2, const float* __restrict__ W3)
{
    int idx = blockIdx.x * blockDim.x + threadIdx.x;   // pair index
    if (idx >= 43520) return;
    int e = idx * 2;
    const float* src; int off; float sc;
    if (e < 65536)      { src = W0; off = e;         sc = 1.0f / 256.0f; }
    else if (e < 81920) { src = W1; off = e - 65536; sc = 1.0f / 128.0f; }
    else if (e < 86016) { src = W2; off = e - 81920; sc = 1.0f / 64.0f; }
    else                { src = W3; off = e - 86016; sc = 1.0f / 32.0f; }
    float2 v = *reinterpret_cast<const float2*>(src + off);
    uint32_t h;
    asm("cvt.rn.f16x2.f32 %0, %1, %2;" : "=r"(h) : "f"(v.y * sc), "f"(v.x * sc));
    reinterpret_cast<uint32_t*>(g_bh)[idx] = h;
}

// ---------------- one irrep-block GEMM (device) ----------------
template<int D, int M, int ROWS, int NU, int WR, int WC>
__device__ __forceinline__
void run_mma(char* sm,
             const float* __restrict__ x, const float* __restrict__ wt,
             float* __restrict__ out, int n0, int nrows, int xo, int wo, int moff)
{
    constexpr int BK  = 16;
    constexpr int SA  = BK + 8;
    constexpr int SB  = M + 8;
    constexpr int KT  = M / BK;
    constexpr int TR  = ROWS / WR, TC = M / WC;
    constexpr int MR  = TR / 16,   MC = TC / 8;
    static_assert(WR * WC == 8 && MR >= 1 && (MC % 2) == 0, "warp grid");
    constexpr int PT  = 256 / ROWS;
    constexpr int EPT = BK / PT;
    constexpr int NP  = EPT / 2;
    static_assert(EPT % 4 == 0, "wt vec4");
    constexpr int XROW = BK * D + 4;
    constexpr int WROW = BK + 4;

    // rings: As x2 (2 fp16 planes each), Bs x4 (1 plane), raw X/W x3
    constexpr uint32_t PS_A   = (uint32_t)ROWS * SA * 2u;
    constexpr uint32_t A_SLOT = 2u * PS_A;
    constexpr uint32_t AS_BYTES = 2u * A_SLOT;
    constexpr uint32_t B_SLOT = (uint32_t)BK * SB * 2u;   // single plane
    constexpr uint32_t BS_BYTES = 4u * B_SLOT;
    constexpr uint32_t X_SLOT = (uint32_t)NU * XROW * 4u;
    constexpr uint32_t W_SLOT = (uint32_t)NU * WROW * 4u;

    const uint32_t smA = (uint32_t)__cvta_generic_to_shared(sm);
    const uint32_t smB = smA + AS_BYTES;
    const uint32_t smX = smB + BS_BYTES;
    const uint32_t smW = smX + 3u * X_SLOT;

    __half* As  = reinterpret_cast<__half*>(sm);
    float*  Xs  = reinterpret_cast<float*>(sm + (smX - smA));
    float*  Wsm = reinterpret_cast<float*>(sm + (smW - smA));

    const int tid = threadIdx.x, lane = tid & 31, wid = tid >> 5;
    const int warpR = wid % WR, warpC = wid / WR;
    const int rw0 = warpR * TR, c0w = warpC * TC;

    const int rfill = tid / PT;
    const int kbase = (tid % PT) * EPT;
    const int nl_f = rfill / D, i_f = rfill - nl_f * D;
    const bool fvalid = (rfill < NU * D) && ((n0 + nl_f) < nrows);

    const uint32_t aAddr0 = smA +
        (uint32_t)(((rw0 + (lane & 15)) * SA + ((lane >> 4) << 3)) * 2);
    const int bg = lane >> 3;
    const uint32_t bAddr0 = smB +
        (uint32_t)(((((bg & 1) << 3) + (lane & 7)) * SB + c0w + ((bg >> 1) << 3)) * 2);

    // ---- hoisted cp.async chunk descriptors ----
    constexpr int BCH = BK * (M / 8);               // single plane
    constexpr int NBC = (BCH + 255) / 256;
    constexpr int XCHR = BK * D / 4;
    constexpr int XCH = NU * XCHR;
    constexpr int NXC = (XCH + 255) / 256;
    constexpr int WCH = NU * (BK / 4);
    constexpr int NWC = 1;

    const char* bsrcp[NBC]; uint32_t bdsto[NBC]; bool bokk[NBC];
    {
        const char* gb = reinterpret_cast<const char*>(g_bh);
#pragma unroll
        for (int i = 0; i < NBC; ++i) {
            int c = tid + i * 256;
            bokk[i] = (c < BCH);
            int cc = bokk[i] ? c : 0;
            int k  = cc / (M / 8);
            int sg = cc - k * (M / 8);
            bdsto[i] = smB + (uint32_t)((k * SB + sg * 8) * 2);
            bsrcp[i] = gb + (size_t)(moff + k * M + sg * 8) * 2;
        }
    }
    const float* xsrcp[NXC]; uint32_t xdsto[NXC]; bool xokk[NXC];
    {
#pragma unroll
        for (int i = 0; i < NXC; ++i) {
            int c = tid + i * 256;
            bool ok = (c < XCH);
            int cc = ok ? c : 0;
            int row = cc / XCHR, sg = cc - row * XCHR;
            xokk[i] = ok && ((n0 + row) < nrows);
            xdsto[i] = smX + (uint32_t)((row * XROW + sg * 4) * 4);
            xsrcp[i] = x + (size_t)(n0 + row) * DIM_ + xo + sg * 4;
        }
    }
    const float* wsrcp[NWC]; uint32_t wdsto[NWC]; bool wokk[NWC];
    {
#pragma unroll
        for (int i = 0; i < NWC; ++i) {
            int c = tid + i * 256;
            bool ok = (c < WCH);
            int cc = ok ? c : 0;
            int row = cc / (BK / 4), sg = cc - row * (BK / 4);
            wokk[i] = ok && ((n0 + row) < nrows);
            wdsto[i] = smW + (uint32_t)((row * WROW + sg * 4) * 4);
            wsrcp[i] = wt + (size_t)(n0 + row) * WNUM_ + wo + sg * 4;
        }
    }

    float acc[MR][MC][4];
#pragma unroll
    for (int a = 0; a < MR; ++a)
#pragma unroll
        for (int b = 0; b < MC; ++b)
#pragma unroll
            for (int c = 0; c < 4; ++c) acc[a][b][c] = 0.0f;

    auto issue_tile = [&](int t) {
        const uint32_t so_b = (uint32_t)(t & 3) * B_SLOT;
        const uint32_t so_x = (uint32_t)(t % 3) * X_SLOT;
        const uint32_t so_w = (uint32_t)(t % 3) * W_SLOT;
#pragma unroll
        for (int i = 0; i < NBC; ++i) {
            if (bokk[i]) cp_async16(bdsto[i] + so_b, bsrcp[i]);
            bsrcp[i] += (size_t)BK * M * 2;
        }
#pragma unroll
        for (int i = 0; i < NXC; ++i) {
            if (xokk[i]) cp_async16(xdsto[i] + so_x, xsrcp[i]);
            xsrcp[i] += BK * D;
        }
#pragma unroll
        for (int i = 0; i < NWC; ++i) {
            if (wokk[i]) cp_async16(wdsto[i] + so_w, wsrcp[i]);
            wsrcp[i] += BK;
        }
    };

    auto split_tile = [&](int t) {
        const int slot = t % 3;
        uint32_t hh[NP], ll[NP];
        if (fvalid) {
            const float* xr = Xs + (size_t)slot * (NU * XROW) + nl_f * XROW + i_f;
            const float* wr = Wsm + (size_t)slot * (NU * WROW) + nl_f * WROW + kbase;
            if constexpr (D == 1) {
#pragma unroll
                for (int v = 0; v < EPT / 4; ++v) {
                    float4 xv = *reinterpret_cast<const float4*>(xr + kbase + 4 * v);
                    float4 wv = *reinterpret_cast<const float4*>(wr + 4 * v);
                    split2h(xv.x * wv.x, xv.y * wv.y, hh[2 * v],     ll[2 * v]);
                    split2h(xv.z * wv.z, xv.w * wv.w, hh[2 * v + 1], ll[2 * v + 1]);
                }
            } else {
                alignas(16) float w[EPT];
#pragma unroll
                for (int v = 0; v < EPT / 4; ++v)
                    reinterpret_cast<float4*>(w)[v] =
                        *reinterpret_cast<const float4*>(wr + 4 * v);
#pragma unroll
                for (int p = 0; p < NP; ++p) {
                    float s0 = xr[(kbase + 2 * p) * D]     * w[2 * p];
                    float s1 = xr[(kbase + 2 * p + 1) * D] * w[2 * p + 1];
                    split2h(s0, s1, hh[p], ll[p]);
                }
            }
        } else {
#pragma unroll
            for (int p = 0; p < NP; ++p) { hh[p] = 0; ll[p] = 0; }
        }
        const uint32_t aOff = (uint32_t)(t & 1) * A_SLOT;
        ull* dh = reinterpret_cast<ull*>(
            reinterpret_cast<char*>(As) + aOff + (rfill * SA + kbase) * 2);
        ull* dl = reinterpret_cast<ull*>(
            reinterpret_cast<char*>(As) + aOff + PS_A + (rfill * SA + kbase) * 2);
#pragma unroll
        for (int q = 0; q < NP / 2; ++q) {
            dh[q] = (ull)hh[2 * q] | ((ull)hh[2 * q + 1] << 32);
            dl[q] = (ull)ll[2 * q] | ((ull)ll[2 * q + 1] << 32);
        }
    };

    // ---- prologue: 2 tiles in flight, split tile 0 ----
    issue_tile(0); cp_commit();
    if (KT > 1) issue_tile(1);
    cp_commit();
    cp_wait1();
    __syncthreads();
    split_tile(0);

    uint32_t ah[MR][4], al[MR][4];

#pragma unroll 1
    for (int t = 0; t < KT; ++t) {
        if (t + 2 < KT) issue_tile(t + 2);
        cp_commit();
        cp_wait1();
        __syncthreads();       // publishes: split(t) STS, raw(t+1), Bs(t+1)

        const uint32_t aBase = aAddr0 + (uint32_t)(t & 1) * A_SLOT;
#pragma unroll
        for (int mr = 0; mr < MR; ++mr) {
            uint32_t a = aBase + (uint32_t)(mr * 16 * SA * 2);
            ldsm4(ah[mr], a);
            ldsm4(al[mr], a + PS_A);
        }

        const uint32_t bBase = bAddr0 + (uint32_t)(t & 3) * B_SLOT;
#pragma unroll
        for (int mc2 = 0; mc2 < MC / 2; ++mc2) {
            uint32_t b = bBase + (uint32_t)(mc2 * 32);
            uint32_t bh[4];
            ldsm4t(bh, b);
#pragma unroll
            for (int mr = 0; mr < MR; ++mr) {
                mma16816h(acc[mr][2 * mc2],     ah[mr], bh[0], bh[1]);
                mma16816h(acc[mr][2 * mc2 + 1], ah[mr], bh[2], bh[3]);
            }
#pragma unroll
            for (int mr = 0; mr < MR; ++mr) {
                mma16816h(acc[mr][2 * mc2],     al[mr], bh[0], bh[1]);
                mma16816h(acc[mr][2 * mc2 + 1], al[mr], bh[2], bh[3]);
            }
        }

        if (t + 1 < KT) split_tile(t + 1);
    }

    // ---- epilogue ----
#pragma unroll
    for (int mr = 0; mr < MR; ++mr) {
#pragma unroll
        for (int half = 0; half < 2; ++half) {
            const int r = rw0 + mr * 16 + (lane >> 2) + half * 8;
            if (r < NU * D) {
                const int nl = r / D, i = r - nl * D;
                const int n = n0 + nl;
                if (n < nrows) {
                    float* orow = out + (size_t)n * DIM_ + xo;
#pragma unroll
                    for (int mc = 0; mc < MC; ++mc) {
                        const int cw = c0w + mc * 8 + 2 * (lane & 3);
                        const float v0 = acc[mr][mc][half * 2];
                        const float v1 = acc[mr][mc][half * 2 + 1];
                        if constexpr (D == 1) {
                            *reinterpret_cast<float2*>(orow + cw) = make_float2(v0, v1);
                        } else {
                            orow[(size_t)cw * D + i]       = v0;
                            orow[(size_t)(cw + 1) * D + i] = v1;
                        }
                    }
                }
            }
        }
    }
}

// ---------------- fused dispatch ----------------
#define CHUNK_CTAS 229
#define CHUNK_ROWS 1600
#define SMEM_DYN 94208

__global__ __launch_bounds__(256, 2)
void tp_mma_fused(const float* __restrict__ x, const float* __restrict__ wt,
                  float* __restrict__ out, int nrows)
{
    extern __shared__ __align__(16) char smraw[];
    const int bid = blockIdx.x;
    const int r = bid / CHUNK_CTAS;
    const int q = bid - r * CHUNK_CTAS;
    const int base = r * CHUNK_ROWS;

    if (q < 25) {
        run_mma<1, 256, 64, 64, 2, 4>(smraw, x, wt, out,
                                      base + q * 64, nrows, 0, 0, 0);
    } else if (q < 65) {
        run_mma<3, 128, 128, 40, 4, 2>(smraw, x, wt, out,
                                       base + (q - 25) * 40, nrows, 256, 256, 65536);
    } else if (q < 129) {
        run_mma<5, 64, 128, 25, 4, 2>(smraw, x, wt, out,
                                      base + (q - 65) * 25, nrows, 640, 384, 81920);
    } else {
        run_mma<7, 32, 128, 16, 8, 1>(smraw, x, wt, out,
                                      base + (q - 129) * 16, nrows, 960, 448, 86016);
    }
}

// ---------------- launch ----------------
extern "C" void kernel_launch(void* const* d_in, const int* in_sizes, int n_in,
                              void* d_out, int out_size)
{
    const float* x  = (const float*)d_in[0];
    const float* wtp = (const float*)d_in[1];
    const float* W0 = (const float*)d_in[2];
    const float* W1 = (const float*)d_in[3];
    const float* W2 = (const float*)d_in[4];
    const float* W3 = (const float*)d_in[5];
    float* out = (float*)d_out;

    const int nrows = in_sizes[0] / DIM_;

    static int attr_set = 0;
    if (!attr_set) {
        cudaFuncSetAttribute(tp_mma_fused,
                             cudaFuncAttributeMaxDynamicSharedMemorySize, SMEM_DYN);
        attr_set = 1;
    }

    split_b_kernel<<<170, 256>>>(W0, W1, W2, W3);

    const int nchunk = (nrows + CHUNK_ROWS - 1) / CHUNK_ROWS;
    tp_mma_fused<<<nchunk * CHUNK_CTAS, 256, SMEM_DYN>>>(x, wtp, out, nrows);
}

// round 17
// speedup vs baseline: 1.6664x; 1.0767x over previous
#include <cuda_runtime.h>
#include <cuda_fp16.h>
#include <cstdint>

// out[n,w,i] = (1/m) * sum_u x[n,u,i] * weight[n,u] * W[u,w]
// Irreps: 256x0e + 128x1o + 64x2e + 32x3o ; DIM=1184, WNUM=480
// R17: single-plane fp16 (1-term mma). S and W each one fp16 plane;
//      rel_err ~2.9e-4 predicted (W-only measured 2.06e-4, add S in quadrature).
//      mma/ldsm/STS/split all halved or better vs R16.

#define DIM_ 1184
#define WNUM_ 480
typedef unsigned long long ull;

// single fp16 plane of W (scaled by 1/m, exact pow2)
__device__ __align__(16) __half g_bh[87040];

__device__ __forceinline__ void cp_async16(uint32_t dst, const void* src) {
    asm volatile("cp.async.cg.shared.global [%0], [%1], 16;" :: "r"(dst), "l"(src));
}
__device__ __forceinline__ void cp_commit() { asm volatile("cp.async.commit_group;"); }
__device__ __forceinline__ void cp_wait1()  { asm volatile("cp.async.wait_group 1;" ::: "memory"); }

__device__ __forceinline__ void ldsm4(uint32_t* r, uint32_t a) {
    asm volatile("ldmatrix.sync.aligned.m8n8.x4.shared.b16 {%0,%1,%2,%3}, [%4];"
                 : "=r"(r[0]), "=r"(r[1]), "=r"(r[2]), "=r"(r[3]) : "r"(a));
}
__device__ __forceinline__ void ldsm4t(uint32_t* r, uint32_t a) {
    asm volatile("ldmatrix.sync.aligned.m8n8.x4.trans.shared.b16 {%0,%1,%2,%3}, [%4];"
                 : "=r"(r[0]), "=r"(r[1]), "=r"(r[2]), "=r"(r[3]) : "r"(a));
}
__device__ __forceinline__ void mma16816h(float* c, const uint32_t* a,
                                          uint32_t b0, uint32_t b1) {
    asm volatile(
        "mma.sync.aligned.m16n8k16.row.col.f32.f16.f16.f32 "
        "{%0,%1,%2,%3}, {%4,%5,%6,%7}, {%8,%9}, {%0,%1,%2,%3};"
        : "+f"(c[0]), "+f"(c[1]), "+f"(c[2]), "+f"(c[3])
        : "r"(a[0]), "r"(a[1]), "r"(a[2]), "r"(a[3]), "r"(b0), "r"(b1));
}

// ---------------- B precompute: fp16, scaled by 1/m (exact pow2) ----------------
__global__ void split_b_kernel(const float* __restrict__ W0, const float* __restrict__ W1,
                               const float* __restrict__ W2, const float* __restrict__ W3)
{
    int idx = blockIdx.x * blockDim.x + threadIdx.x;   // pair index
    if (idx >= 43520) return;
    int e = idx * 2;
    const float* src; int off; float sc;
    if (e < 65536)      { src = W0; off = e;         sc = 1.0f / 256.0f; }
    else if (e < 81920) { src = W1; off = e - 65536; sc = 1.0f / 128.0f; }
    else if (e < 86016) { src = W2; off = e - 81920; sc = 1.0f / 64.0f; }
    else                { src = W3; off = e - 86016; sc = 1.0f / 32.0f; }
    float2 v = *reinterpret_cast<const float2*>(src + off);
    uint32_t h;
    asm("cvt.rn.f16x2.f32 %0, %1, %2;" : "=r"(h) : "f"(v.y * sc), "f"(v.x * sc));
    reinterpret_cast<uint32_t*>(g_bh)[idx] = h;
}

// ---------------- one irrep-block GEMM (device) ----------------
template<int D, int M, int ROWS, int NU, int WR, int WC>
__device__ __forceinline__
void run_mma(char* sm,
             const float* __restrict__ x, const float* __restrict__ wt,
             float* __restrict__ out, int n0, int nrows, int xo, int wo, int moff)
{
    constexpr int BK  = 16;
    constexpr int SA  = BK + 8;
    constexpr int SB  = M + 8;
    constexpr int KT  = M / BK;
    constexpr int TR  = ROWS / WR, TC = M / WC;
    constexpr int MR  = TR / 16,   MC = TC / 8;
    static_assert(WR * WC == 8 && MR >= 1 && (MC % 2) == 0, "warp grid");
    constexpr int PT  = 256 / ROWS;
    constexpr int EPT = BK / PT;
    constexpr int NP  = EPT / 2;
    static_assert(EPT % 4 == 0, "wt vec4");
    constexpr int XROW = BK * D + 4;
    constexpr int WROW = BK + 4;

    // rings: As x2 (ONE fp16 plane each), Bs x4 (1 plane), raw X/W x3
    constexpr uint32_t PS_A   = (uint32_t)ROWS * SA * 2u;
    constexpr uint32_t A_SLOT = PS_A;
    constexpr uint32_t AS_BYTES = 2u * A_SLOT;
    constexpr uint32_t B_SLOT = (uint32_t)BK * SB * 2u;
    constexpr uint32_t BS_BYTES = 4u * B_SLOT;
    constexpr uint32_t X_SLOT = (uint32_t)NU * XROW * 4u;
    constexpr uint32_t W_SLOT = (uint32_t)NU * WROW * 4u;

    const uint32_t smA = (uint32_t)__cvta_generic_to_shared(sm);
    const uint32_t smB = smA + AS_BYTES;
    const uint32_t smX = smB + BS_BYTES;
    const uint32_t smW = smX + 3u * X_SLOT;

    __half* As  = reinterpret_cast<__half*>(sm);
    float*  Xs  = reinterpret_cast<float*>(sm + (smX - smA));
    float*  Wsm = reinterpret_cast<float*>(sm + (smW - smA));

    const int tid = threadIdx.x, lane = tid & 31, wid = tid >> 5;
    const int warpR = wid % WR, warpC = wid / WR;
    const int rw0 = warpR * TR, c0w = warpC * TC;

    const int rfill = tid / PT;
    const int kbase = (tid % PT) * EPT;
    const int nl_f = rfill / D, i_f = rfill - nl_f * D;
    const bool fvalid = (rfill < NU * D) && ((n0 + nl_f) < nrows);

    const uint32_t aAddr0 = smA +
        (uint32_t)(((rw0 + (lane & 15)) * SA + ((lane >> 4) << 3)) * 2);
    const int bg = lane >> 3;
    const uint32_t bAddr0 = smB +
        (uint32_t)(((((bg & 1) << 3) + (lane & 7)) * SB + c0w + ((bg >> 1) << 3)) * 2);

    // ---- hoisted cp.async chunk descriptors ----
    constexpr int BCH = BK * (M / 8);
    constexpr int NBC = (BCH + 255) / 256;
    constexpr int XCHR = BK * D / 4;
    constexpr int XCH = NU * XCHR;
    constexpr int NXC = (XCH + 255) / 256;
    constexpr int WCH = NU * (BK / 4);
    constexpr int NWC = 1;

    const char* bsrcp[NBC]; uint32_t bdsto[NBC]; bool bokk[NBC];
    {
        const char* gb = reinterpret_cast<const char*>(g_bh);
#pragma unroll
        for (int i = 0; i < NBC; ++i) {
            int c = tid + i * 256;
            bokk[i] = (c < BCH);
            int cc = bokk[i] ? c : 0;
            int k  = cc / (M / 8);
            int sg = cc - k * (M / 8);
            bdsto[i] = smB + (uint32_t)((k * SB + sg * 8) * 2);
            bsrcp[i] = gb + (size_t)(moff + k * M + sg * 8) * 2;
        }
    }
    const float* xsrcp[NXC]; uint32_t xdsto[NXC]; bool xokk[NXC];
    {
#pragma unroll
        for (int i = 0; i < NXC; ++i) {
            int c = tid + i * 256;
            bool ok = (c < XCH);
            int cc = ok ? c : 0;
            int row = cc / XCHR, sg = cc - row * XCHR;
            xokk[i] = ok && ((n0 + row) < nrows);
            xdsto[i] = smX + (uint32_t)((row * XROW + sg * 4) * 4);
            xsrcp[i] = x + (size_t)(n0 + row) * DIM_ + xo + sg * 4;
        }
    }
    const float* wsrcp[NWC]; uint32_t wdsto[NWC]; bool wokk[NWC];
    {
#pragma unroll
        for (int i = 0; i < NWC; ++i) {
            int c = tid + i * 256;
            bool ok = (c < WCH);
            int cc = ok ? c : 0;
            int row = cc / (BK / 4), sg = cc - row * (BK / 4);
            wokk[i] = ok && ((n0 + row) < nrows);
            wdsto[i] = smW + (uint32_t)((row * WROW + sg * 4) * 4);
            wsrcp[i] = wt + (size_t)(n0 + row) * WNUM_ + wo + sg * 4;
        }
    }

    float acc[MR][MC][4];
#pragma unroll
    for (int a = 0; a < MR; ++a)
#pragma unroll
        for (int b = 0; b < MC; ++b)
#pragma unroll
            for (int c = 0; c < 4; ++c) acc[a][b][c] = 0.0f;

    auto issue_tile = [&](int t) {
        const uint32_t so_b = (uint32_t)(t & 3) * B_SLOT;
        const uint32_t so_x = (uint32_t)(t % 3) * X_SLOT;
        const uint32_t so_w = (uint32_t)(t % 3) * W_SLOT;
#pragma unroll
        for (int i = 0; i < NBC; ++i) {
            if (bokk[i]) cp_async16(bdsto[i] + so_b, bsrcp[i]);
            bsrcp[i] += (size_t)BK * M * 2;
        }
#pragma unroll
        for (int i = 0; i < NXC; ++i) {
            if (xokk[i]) cp_async16(xdsto[i] + so_x, xsrcp[i]);
            xsrcp[i] += BK * D;
        }
#pragma unroll
        for (int i = 0; i < NWC; ++i) {
            if (wokk[i]) cp_async16(wdsto[i] + so_w, wsrcp[i]);
            wsrcp[i] += BK;
        }
    };

    auto split_tile = [&](int t) {
        const int slot = t % 3;
        uint32_t hh[NP];
        if (fvalid) {
            const float* xr = Xs + (size_t)slot * (NU * XROW) + nl_f * XROW + i_f;
            const float* wr = Wsm + (size_t)slot * (NU * WROW) + nl_f * WROW + kbase;
            if constexpr (D == 1) {
#pragma unroll
                for (int v = 0; v < EPT / 4; ++v) {
                    float4 xv = *reinterpret_cast<const float4*>(xr + kbase + 4 * v);
                    float4 wv = *reinterpret_cast<const float4*>(wr + 4 * v);
                    asm("cvt.rn.f16x2.f32 %0, %1, %2;"
                        : "=r"(hh[2 * v]) : "f"(xv.y * wv.y), "f"(xv.x * wv.x));
                    asm("cvt.rn.f16x2.f32 %0, %1, %2;"
                        : "=r"(hh[2 * v + 1]) : "f"(xv.w * wv.w), "f"(xv.z * wv.z));
                }
            } else {
                alignas(16) float w[EPT];
#pragma unroll
                for (int v = 0; v < EPT / 4; ++v)
                    reinterpret_cast<float4*>(w)[v] =
                        *reinterpret_cast<const float4*>(wr + 4 * v);
#pragma unroll
                for (int p = 0; p < NP; ++p) {
                    float s0 = xr[(kbase + 2 * p) * D]     * w[2 * p];
                    float s1 = xr[(kbase + 2 * p + 1) * D] * w[2 * p + 1];
                    asm("cvt.rn.f16x2.f32 %0, %1, %2;"
                        : "=r"(hh[p]) : "f"(s1), "f"(s0));
                }
            }
        } else {
#pragma unroll
            for (int p = 0; p < NP; ++p) hh[p] = 0;
        }
        const uint32_t aOff = (uint32_t)(t & 1) * A_SLOT;
        ull* dh = reinterpret_cast<ull*>(
            reinterpret_cast<char*>(As) + aOff + (rfill * SA + kbase) * 2);
#pragma unroll
        for (int q = 0; q < NP / 2; ++q)
            dh[q] = (ull)hh[2 * q] | ((ull)hh[2 * q + 1] << 32);
    };

    // ---- prologue: 2 tiles in flight, split tile 0 ----
    issue_tile(0); cp_commit();
    if (KT > 1) issue_tile(1);
    cp_commit();
    cp_wait1();
    __syncthreads();
    split_tile(0);

    uint32_t ah[MR][4];

#pragma unroll 1
    for (int t = 0; t < KT; ++t) {
        if (t + 2 < KT) issue_tile(t + 2);
        cp_commit();
        cp_wait1();
        __syncthreads();       // publishes: split(t) STS, raw(t+1), Bs(t+1)

        const uint32_t aBase = aAddr0 + (uint32_t)(t & 1) * A_SLOT;
#pragma unroll
        for (int mr = 0; mr < MR; ++mr)
            ldsm4(ah[mr], aBase + (uint32_t)(mr * 16 * SA * 2));

        const uint32_t bBase = bAddr0 + (uint32_t)(t & 3) * B_SLOT;
#pragma unroll
        for (int mc2 = 0; mc2 < MC / 2; ++mc2) {
            uint32_t b = bBase + (uint32_t)(mc2 * 32);
            uint32_t bh[4];
            ldsm4t(bh, b);
#pragma unroll
            for (int mr = 0; mr < MR; ++mr) {
                mma16816h(acc[mr][2 * mc2],     ah[mr], bh[0], bh[1]);
                mma16816h(acc[mr][2 * mc2 + 1], ah[mr], bh[2], bh[3]);
            }
        }

        if (t + 1 < KT) split_tile(t + 1);
    }

    // ---- epilogue ----
#pragma unroll
    for (int mr = 0; mr < MR; ++mr) {
#pragma unroll
        for (int half = 0; half < 2; ++half) {
            const int r = rw0 + mr * 16 + (lane >> 2) + half * 8;
            if (r < NU * D) {
                const int nl = r / D, i = r - nl * D;
                const int n = n0 + nl;
                if (n < nrows) {
                    float* orow = out + (size_t)n * DIM_ + xo;
#pragma unroll
                    for (int mc = 0; mc < MC; ++mc) {
                        const int cw = c0w + mc * 8 + 2 * (lane & 3);
                        const float v0 = acc[mr][mc][half * 2];
                        const float v1 = acc[mr][mc][half * 2 + 1];
                        if constexpr (D == 1) {
                            *reinterpret_cast<float2*>(orow + cw) = make_float2(v0, v1);
                        } else {
                            orow[(size_t)cw * D + i]       = v0;
                            orow[(size_t)(cw + 1) * D + i] = v1;
                        }
                    }
                }
            }
        }
    }
}

// ---------------- fused dispatch ----------------
#define CHUNK_CTAS 229
#define CHUNK_ROWS 1600
#define SMEM_DYN 71680

__global__ __launch_bounds__(256, 2)
void tp_mma_fused(const float* __restrict__ x, const float* __restrict__ wt,
                  float* __restrict__ out, int nrows)
{
    extern __shared__ __align__(16) char smraw[];
    const int bid = blockIdx.x;
    const int r = bid / CHUNK_CTAS;
    const int q = bid - r * CHUNK_CTAS;
    const int base = r * CHUNK_ROWS;

    if (q < 25) {
        run_mma<1, 256, 64, 64, 2, 4>(smraw, x, wt, out,
                                      base + q * 64, nrows, 0, 0, 0);
    } else if (q < 65) {
        run_mma<3, 128, 128, 40, 4, 2>(smraw, x, wt, out,
                                       base + (q - 25) * 40, nrows, 256, 256, 65536);
    } else if (q < 129) {
        run_mma<5, 64, 128, 25, 4, 2>(smraw, x, wt, out,
                                      base + (q - 65) * 25, nrows, 640, 384, 81920);
    } else {
        run_mma<7, 32, 128, 16, 8, 1>(smraw, x, wt, out,
                                      base + (q - 129) * 16, nrows, 960, 448, 86016);
    }
}

// ---------------- launch ----------------
extern "C" void kernel_launch(void* const* d_in, const int* in_sizes, int n_in,
                              void* d_out, int out_size)
{
    const float* x  = (const float*)d_in[0];
    const float* wtp = (const float*)d_in[1];
    const float* W0 = (const float*)d_in[2];
    const float* W1 = (const float*)d_in[3];
    const float* W2 = (const float*)d_in[4];
    const float* W3 = (const float*)d_in[5];
    float* out = (float*)d_out;

    const int nrows = in_sizes[0] / DIM_;

    static int attr_set = 0;
    if (!attr_set) {
        cudaFuncSetAttribute(tp_mma_fused,
                             cudaFuncAttributeMaxDynamicSharedMemorySize, SMEM_DYN);
        attr_set = 1;
    }

    split_b_kernel<<<170, 256>>>(W0, W1, W2, W3);

    const int nchunk = (nrows + CHUNK_ROWS - 1) / CHUNK_ROWS;
    tp_mma_fused<<<nchunk * CHUNK_CTAS, 256, SMEM_DYN>>>(x, wtp, out, nrows);
}